// round 1
// baseline (speedup 1.0000x reference)
#include <cuda_runtime.h>
#include <cstddef>

// Problem constants
#define CB 8
#define CS 512
#define CE 512
#define CH 8
#define CD 64
#define CP 64
#define CF 2048
#define CNR 129            // 2P+1
#define CSR 192            // padded stride for bins / pos_emb (3 chunks of 64)
#define CBH (CB*CH)        // 64
#define CM (CB*CS)         // 4096

// ---------------- device scratch (zero-initialized .bss; padding rows stay 0) ----
__device__ __align__(16) float g_q[CBH*CS*CD];
__device__ __align__(16) float g_k[CBH*CS*CD];
__device__ __align__(16) float g_v[CBH*CS*CD];
__device__ __align__(16) float g_qz[CBH*CS*CNR];
__device__ __align__(16) float g_w[CBH*CS*CS];          // scores -> aw (in place)
__device__ __align__(16) float g_s[CBH*CS*CSR];         // softmax bins (padded, tail stays 0)
__device__ __align__(16) float g_pe[CSR*CD];            // padded pos_emb (tail stays 0)
__device__ __align__(16) float g_concat[CM*CE];
__device__ __align__(16) float g_t1[CM*CE];
__device__ __align__(16) float g_attnout[CM*CE];
__device__ __align__(16) float g_hidden[CM*CF];
__device__ __align__(16) float g_t2[CM*CE];

enum { EPI_QKV = 0, EPI_RESID = 1, EPI_RELU = 2 };

// ---------------- generic SGEMM: C = A(MxK) @ B(KxN) + epilogue --------------
__global__ __launch_bounds__(256) void sgemm_kernel(
    const float* __restrict__ A, const float* __restrict__ Bm,
    float* __restrict__ C, int M, int N, int K,
    const float* __restrict__ bias, const float* __restrict__ resid, int mode)
{
    __shared__ float As[8][128];
    __shared__ float Bs[8][128];
    const int tid = threadIdx.x;
    const int bm = blockIdx.y * 128;
    const int bn = blockIdx.x * 128;
    const int a_row = tid >> 1;
    const int a_col = (tid & 1) << 2;
    const int b_row = tid >> 5;
    const int b_col = (tid & 31) << 2;
    const int tx = (tid & 15) << 3;
    const int ty = (tid >> 4) << 3;

    float acc[8][8];
#pragma unroll
    for (int i = 0; i < 8; i++)
#pragma unroll
        for (int j = 0; j < 8; j++) acc[i][j] = 0.0f;

    const float* Ap = A + (size_t)(bm + a_row) * K + a_col;
    const float* Bp = Bm + (size_t)b_row * N + bn + b_col;

    for (int k0 = 0; k0 < K; k0 += 8) {
        float4 av = *(const float4*)(Ap + k0);
        float4 bv = *(const float4*)(Bp + (size_t)k0 * N);
        As[a_col + 0][a_row] = av.x;
        As[a_col + 1][a_row] = av.y;
        As[a_col + 2][a_row] = av.z;
        As[a_col + 3][a_row] = av.w;
        *(float4*)&Bs[b_row][b_col] = bv;
        __syncthreads();
#pragma unroll
        for (int kk = 0; kk < 8; kk++) {
            float4 a0 = *(const float4*)&As[kk][ty];
            float4 a1 = *(const float4*)&As[kk][ty + 4];
            float4 b0 = *(const float4*)&Bs[kk][tx];
            float4 b1 = *(const float4*)&Bs[kk][tx + 4];
            float ar[8] = {a0.x, a0.y, a0.z, a0.w, a1.x, a1.y, a1.z, a1.w};
            float br[8] = {b0.x, b0.y, b0.z, b0.w, b1.x, b1.y, b1.z, b1.w};
#pragma unroll
            for (int i = 0; i < 8; i++)
#pragma unroll
                for (int j = 0; j < 8; j++)
                    acc[i][j] = fmaf(ar[i], br[j], acc[i][j]);
        }
        __syncthreads();
    }

#pragma unroll
    for (int i = 0; i < 8; i++) {
        const int row = bm + ty + i;
#pragma unroll
        for (int j = 0; j < 8; j++) {
            const int col = bn + tx + j;
            float v = acc[i][j];
            if (bias) v += bias[col];
            if (mode == EPI_RESID) v += resid[(size_t)row * N + col];
            else if (mode == EPI_RELU) v = fmaxf(v, 0.0f);
            if (mode == EPI_QKV) {
                const int b = row >> 9, ii = row & 511;
                const int h = col >> 6, d = col & 63;
                C[(((size_t)(b * CH + h) * CS) + ii) * CD + d] = v;
            } else {
                C[(size_t)row * N + col] = v;
            }
        }
    }
}

// ---------------- pad pos_emb into g_pe ---------------------------------------
__global__ void pe_copy_kernel(const float* __restrict__ pe)
{
    int t = blockIdx.x * 256 + threadIdx.x;
    if (t < CNR * CD) g_pe[t] = pe[t];
}

// ---------------- qz table: (BH*S, 129) = Q2d(32768x64) @ pos_emb^T -----------
__global__ __launch_bounds__(256) void qz_kernel(const float* __restrict__ pe)
{
    const int m0 = blockIdx.x << 5;  // 32 q rows
    __shared__ float Qs[32 * 64];
    __shared__ float PEs[CNR * 64];
    const int tid = threadIdx.x;

    const float4* qsrc = (const float4*)(g_q + (size_t)m0 * CD);
    float4* qdst = (float4*)Qs;
    for (int t = tid; t < 32 * 16; t += 256) qdst[t] = qsrc[t];
    const float4* psrc = (const float4*)pe;
    float4* pdst = (float4*)PEs;
    for (int t = tid; t < CNR * 16; t += 256) pdst[t] = psrc[t];
    __syncthreads();

    for (int o = tid; o < 32 * CNR; o += 256) {
        const int i = o / CNR;
        const int r = o - i * CNR;
        const float* qq = Qs + i * 64;
        const float* pp = PEs + r * 64;
        float s = 0.0f;
#pragma unroll
        for (int d = 0; d < 64; d++) s = fmaf(qq[d], pp[d], s);
        g_qz[(size_t)(m0 + i) * CNR + r] = s;
    }
}

// ---------------- scores: w = (q.k + qz[idx])*scale + 0.6*dist, mask ----------
__global__ __launch_bounds__(256) void scores_kernel(
    const float* __restrict__ dist, const int* __restrict__ dt,
    const int* __restrict__ mask)
{
    const int bh = blockIdx.z;
    const int b = bh >> 3;
    const int i0 = blockIdx.y << 6;
    const int j0 = blockIdx.x << 6;

    __shared__ float Qt[64][68];   // [d][i]
    __shared__ float Kt[64][68];   // [d][j]
    __shared__ int dti[64], dtj[64], mj[64];

    const float* qb = g_q + (size_t)bh * CS * CD;
    const float* kb = g_k + (size_t)bh * CS * CD;
    const int tid = threadIdx.x;

#pragma unroll
    for (int l = 0; l < 4; l++) {
        const int idx = tid + (l << 8);
        const int r = idx >> 4;
        const int c = (idx & 15) << 2;
        float4 qv = *(const float4*)(qb + (size_t)(i0 + r) * CD + c);
        float4 kv = *(const float4*)(kb + (size_t)(j0 + r) * CD + c);
        Qt[c + 0][r] = qv.x; Qt[c + 1][r] = qv.y; Qt[c + 2][r] = qv.z; Qt[c + 3][r] = qv.w;
        Kt[c + 0][r] = kv.x; Kt[c + 1][r] = kv.y; Kt[c + 2][r] = kv.z; Kt[c + 3][r] = kv.w;
    }
    if (tid < 64) {
        dti[tid] = dt[b * CS + i0 + tid];
        dtj[tid] = dt[b * CS + j0 + tid];
        mj[tid] = mask[b * CS + j0 + tid];
    }
    __syncthreads();

    const int ty4 = (tid >> 4) << 2;   // i
    const int tx4 = (tid & 15) << 2;   // j
    float acc[4][4];
#pragma unroll
    for (int i = 0; i < 4; i++)
#pragma unroll
        for (int j = 0; j < 4; j++) acc[i][j] = 0.0f;

#pragma unroll
    for (int k = 0; k < 64; k++) {
        float4 a4 = *(const float4*)&Qt[k][ty4];
        float4 b4 = *(const float4*)&Kt[k][tx4];
        float ar[4] = {a4.x, a4.y, a4.z, a4.w};
        float br[4] = {b4.x, b4.y, b4.z, b4.w};
#pragma unroll
        for (int i = 0; i < 4; i++)
#pragma unroll
            for (int j = 0; j < 4; j++)
                acc[i][j] = fmaf(ar[i], br[j], acc[i][j]);
    }

#pragma unroll
    for (int ii = 0; ii < 4; ii++) {
        const int i = i0 + ty4 + ii;
        const int di = dti[ty4 + ii];
#pragma unroll
        for (int jj = 0; jj < 4; jj++) {
            const int j = j0 + tx4 + jj;
            int rel = dtj[tx4 + jj] - di;
            rel = min(max(rel, -CP), CP) + CP;
            const float qzv = g_qz[((size_t)bh * CS + i) * CNR + rel];
            float v = (acc[ii][jj] + qzv) * 0.125f
                    + 0.6f * dist[((size_t)b * CS + i) * CS + j];
            if (mj[tx4 + jj] == 0) v = -1e9f;
            g_w[((size_t)bh * CS + i) * CS + j] = v;
        }
    }
}

// ---------------- softmax + 129-bin histogram ---------------------------------
__global__ __launch_bounds__(256) void softmax_kernel(const int* __restrict__ dt)
{
    const int row = blockIdx.x;           // bh*S + i
    const int bh = row >> 9;
    const int i = row & 511;
    const int b = bh >> 3;
    float* wr = g_w + (size_t)row * CS;
    const int tid = threadIdx.x;

    __shared__ float red[256];
    __shared__ float bins[CNR];

    float v0 = wr[tid], v1 = wr[tid + 256];
    red[tid] = fmaxf(v0, v1);
    __syncthreads();
    for (int s = 128; s > 0; s >>= 1) {
        if (tid < s) red[tid] = fmaxf(red[tid], red[tid + s]);
        __syncthreads();
    }
    const float mx = red[0];
    __syncthreads();

    const float e0 = __expf(v0 - mx);
    const float e1 = __expf(v1 - mx);
    red[tid] = e0 + e1;
    __syncthreads();
    for (int s = 128; s > 0; s >>= 1) {
        if (tid < s) red[tid] += red[tid + s];
        __syncthreads();
    }
    const float inv = 1.0f / red[0];
    if (tid < CNR) bins[tid] = 0.0f;
    __syncthreads();

    const float a0 = e0 * inv, a1 = e1 * inv;
    wr[tid] = a0;
    wr[tid + 256] = a1;

    const int di = dt[b * CS + i];
    int r0 = min(max(dt[b * CS + tid] - di, -CP), CP) + CP;
    int r1 = min(max(dt[b * CS + tid + 256] - di, -CP), CP) + CP;
    atomicAdd(&bins[r0], a0);
    atomicAdd(&bins[r1], a1);
    __syncthreads();
    if (tid < CNR) g_s[(size_t)row * CSR + tid] = bins[tid];
}

// ---------------- attn = aw@v + bins@pos_emb -> concat layout -----------------
__global__ __launch_bounds__(256) void attn_kernel()
{
    const int bh = blockIdx.y;
    const int b = bh >> 3, h = bh & 7;
    const int i0 = blockIdx.x << 6;
    const int tid = threadIdx.x;

    __shared__ float At[64][68];   // [k][i]
    __shared__ float Vs[64][64];   // [k][d]

    const float* awb = g_w + (size_t)bh * CS * CS;
    const float* sb = g_s + (size_t)bh * CS * CSR;
    const float* vb = g_v + (size_t)bh * CS * CD;

    const int ty4 = (tid >> 4) << 2;   // i
    const int tx4 = (tid & 15) << 2;   // d
    float acc[4][4];
#pragma unroll
    for (int i = 0; i < 4; i++)
#pragma unroll
        for (int j = 0; j < 4; j++) acc[i][j] = 0.0f;

    for (int c = 0; c < 11; c++) {
#pragma unroll
        for (int l = 0; l < 4; l++) {
            const int idx = tid + (l << 8);
            const int r = idx >> 4;
            const int cc = (idx & 15) << 2;
            float4 av, vv;
            if (c < 8) {
                av = *(const float4*)(awb + (size_t)(i0 + r) * CS + (c << 6) + cc);
                vv = *(const float4*)(vb + (size_t)((c << 6) + r) * CD + cc);
            } else {
                av = *(const float4*)(sb + (size_t)(i0 + r) * CSR + ((c - 8) << 6) + cc);
                vv = *(const float4*)(g_pe + (size_t)(((c - 8) << 6) + r) * CD + cc);
            }
            At[cc + 0][r] = av.x; At[cc + 1][r] = av.y; At[cc + 2][r] = av.z; At[cc + 3][r] = av.w;
            *(float4*)&Vs[r][cc] = vv;
        }
        __syncthreads();
#pragma unroll
        for (int k = 0; k < 64; k++) {
            float4 a4 = *(const float4*)&At[k][ty4];
            float4 v4 = *(const float4*)&Vs[k][tx4];
            float ar[4] = {a4.x, a4.y, a4.z, a4.w};
            float vr[4] = {v4.x, v4.y, v4.z, v4.w};
#pragma unroll
            for (int i = 0; i < 4; i++)
#pragma unroll
                for (int j = 0; j < 4; j++)
                    acc[i][j] = fmaf(ar[i], vr[j], acc[i][j]);
        }
        __syncthreads();
    }

#pragma unroll
    for (int ii = 0; ii < 4; ii++)
#pragma unroll
        for (int jj = 0; jj < 4; jj++)
            g_concat[(size_t)(b * CS + i0 + ty4 + ii) * CE + h * CD + tx4 + jj] = acc[ii][jj];
}

// ---------------- layernorm (row = 512) ---------------------------------------
__global__ __launch_bounds__(256) void ln_kernel(
    const float* __restrict__ in, float* __restrict__ out,
    const float* __restrict__ gg, const float* __restrict__ bb)
{
    const int row = blockIdx.x;
    const float* xr = in + (size_t)row * CE;
    const int tid = threadIdx.x;
    __shared__ float red[256];

    float v0 = xr[tid], v1 = xr[tid + 256];
    red[tid] = v0 + v1;
    __syncthreads();
    for (int s = 128; s > 0; s >>= 1) {
        if (tid < s) red[tid] += red[tid + s];
        __syncthreads();
    }
    const float mu = red[0] * (1.0f / CE);
    __syncthreads();
    const float d0 = v0 - mu, d1 = v1 - mu;
    red[tid] = d0 * d0 + d1 * d1;
    __syncthreads();
    for (int s = 128; s > 0; s >>= 1) {
        if (tid < s) red[tid] += red[tid + s];
        __syncthreads();
    }
    const float rstd = rsqrtf(red[0] * (1.0f / CE) + 1e-5f);
    out[(size_t)row * CE + tid] = d0 * rstd * gg[tid] + bb[tid];
    out[(size_t)row * CE + tid + 256] = d1 * rstd * gg[tid + 256] + bb[tid + 256];
}

// ---------------- launch -------------------------------------------------------
extern "C" void kernel_launch(void* const* d_in, const int* in_sizes, int n_in,
                              void* d_out, int out_size)
{
    const float* x    = (const float*)d_in[0];
    const float* dist = (const float*)d_in[1];
    const int*   dt   = (const int*)d_in[2];
    const int*   mask = (const int*)d_in[3];
    const float* wq_w = (const float*)d_in[4];
    const float* wq_b = (const float*)d_in[5];
    const float* wk_w = (const float*)d_in[6];
    const float* wk_b = (const float*)d_in[7];
    const float* wv_w = (const float*)d_in[8];
    const float* wv_b = (const float*)d_in[9];
    const float* wo_w = (const float*)d_in[10];
    const float* wo_b = (const float*)d_in[11];
    const float* pe   = (const float*)d_in[12];
    const float* w1   = (const float*)d_in[13];
    const float* b1   = (const float*)d_in[14];
    const float* w2   = (const float*)d_in[15];
    const float* b2   = (const float*)d_in[16];
    const float* ln1g = (const float*)d_in[17];
    const float* ln1b = (const float*)d_in[18];
    const float* ln2g = (const float*)d_in[19];
    const float* ln2b = (const float*)d_in[20];
    float* out = (float*)d_out;

    void *pq, *pk, *pv, *pcc, *pt1, *pao, *phid, *pt2;
    cudaGetSymbolAddress(&pq, g_q);
    cudaGetSymbolAddress(&pk, g_k);
    cudaGetSymbolAddress(&pv, g_v);
    cudaGetSymbolAddress(&pcc, g_concat);
    cudaGetSymbolAddress(&pt1, g_t1);
    cudaGetSymbolAddress(&pao, g_attnout);
    cudaGetSymbolAddress(&phid, g_hidden);
    cudaGetSymbolAddress(&pt2, g_t2);

    pe_copy_kernel<<<(CNR * CD + 255) / 256, 256>>>(pe);

    dim3 gqkv(CE / 128, CM / 128);
    sgemm_kernel<<<gqkv, 256>>>(x, wq_w, (float*)pq, CM, CE, CE, wq_b, nullptr, EPI_QKV);
    sgemm_kernel<<<gqkv, 256>>>(x, wk_w, (float*)pk, CM, CE, CE, wk_b, nullptr, EPI_QKV);
    sgemm_kernel<<<gqkv, 256>>>(x, wv_w, (float*)pv, CM, CE, CE, wv_b, nullptr, EPI_QKV);

    qz_kernel<<<(CBH * CS) / 32, 256>>>(pe);

    dim3 gsc(CS / 64, CS / 64, CBH);
    scores_kernel<<<gsc, 256>>>(dist, dt, mask);

    softmax_kernel<<<CBH * CS, 256>>>(dt);

    dim3 gat(CS / 64, CBH);
    attn_kernel<<<gat, 256>>>();

    sgemm_kernel<<<gqkv, 256>>>((const float*)pcc, wo_w, (float*)pt1, CM, CE, CE, wo_b, x, EPI_RESID);
    ln_kernel<<<CM, 256>>>((const float*)pt1, (float*)pao, ln1g, ln1b);

    dim3 gf1(CF / 128, CM / 128);
    sgemm_kernel<<<gf1, 256>>>((const float*)pao, w1, (float*)phid, CM, CF, CE, b1, nullptr, EPI_RELU);
    sgemm_kernel<<<gqkv, 256>>>((const float*)phid, w2, (float*)pt2, CM, CE, CF, b2, (const float*)pao, EPI_RESID);
    ln_kernel<<<CM, 256>>>((const float*)pt2, out, ln2g, ln2b);
}

// round 2
// speedup vs baseline: 1.6384x; 1.6384x over previous
#include <cuda_runtime.h>
#include <cstdint>
#include <cstddef>

// Problem constants
#define CB 8
#define CS 512
#define CE 512
#define CH 8
#define CD 64
#define CP 64
#define CF 2048
#define CNR 129            // 2P+1
#define CSR 192            // padded stride for bins / pos_emb (3 chunks of 64)
#define CBH (CB*CH)        // 64
#define CM (CB*CS)         // 4096

// ---------------- device scratch (zero-initialized .bss) ----------------------
__device__ __align__(16) float g_q[CBH*CS*CD];
__device__ __align__(16) float g_k[CBH*CS*CD];
__device__ __align__(16) float g_v[CBH*CS*CD];
__device__ __align__(16) float g_qz[CBH*CS*CNR];
__device__ __align__(16) float g_w[CBH*CS*CS];          // scores -> aw (in place)
__device__ __align__(16) float g_s[CBH*CS*CSR];         // softmax bins (padded)
__device__ __align__(16) float g_pe[CSR*CD];            // padded pos_emb
__device__ __align__(16) float g_concat[CM*CE];
__device__ __align__(16) float g_t1[CM*CE];
__device__ __align__(16) float g_attnout[CM*CE];
__device__ __align__(16) float g_hidden[CM*CF];
__device__ __align__(16) float g_t2[CM*CE];

enum { EPI_QKV = 0, EPI_RESID = 1, EPI_RELU = 2 };

__device__ __forceinline__ uint32_t f2tf(float f) {
    uint32_t u;
    asm("cvt.rna.tf32.f32 %0, %1;" : "=r"(u) : "f"(f));
    return u;
}

__device__ __forceinline__ void mma_tf32(float c[4], const uint32_t a[4],
                                         const uint32_t b[2]) {
    asm volatile(
        "mma.sync.aligned.m16n8k8.row.col.f32.tf32.tf32.f32 "
        "{%0,%1,%2,%3}, {%4,%5,%6,%7}, {%8,%9}, {%0,%1,%2,%3};\n"
        : "+f"(c[0]), "+f"(c[1]), "+f"(c[2]), "+f"(c[3])
        : "r"(a[0]), "r"(a[1]), "r"(a[2]), "r"(a[3]), "r"(b[0]), "r"(b[1]));
}

// ---------------- TF32 tensor-core GEMM: C = A(MxK)@B(KxN) + epilogue ---------
// Block tile 128x128, BK=16, 8 warps (4x2), warp tile 32x64.
#define APITCH 20
#define BPITCH 132

__global__ __launch_bounds__(256) void mma_gemm_kernel(
    const float* __restrict__ A, const float* __restrict__ Bm,
    float* __restrict__ C, int M, int N, int K,
    const float* __restrict__ bias, const float* __restrict__ resid, int mode)
{
    __shared__ uint32_t As[2][128 * APITCH];
    __shared__ uint32_t Bs[2][16 * BPITCH];

    const int tid = threadIdx.x;
    const int warp = tid >> 5;
    const int lane = tid & 31;
    const int gid = lane >> 2;
    const int tig = lane & 3;
    const int wy = warp >> 1;     // 0..3 (M)
    const int wx = warp & 1;      // 0..1 (N)
    const int bm = blockIdx.y * 128;
    const int bn = blockIdx.x * 128;

    // global load indices
    const int ar = tid >> 1;                 // A row in tile (0..127)
    const int ak = (tid & 1) << 3;           // A k base (0 or 8)
    const int br = tid >> 4;                 // B k row in tile (0..15)
    const int bc = (tid & 15) << 2;          // B col base (0..60 step 4)

    const float* Ap = A + (size_t)(bm + ar) * K + ak;
    const float* Bp = Bm + (size_t)br * N + bn + bc;

    float acc[2][8][4];
#pragma unroll
    for (int mt = 0; mt < 2; mt++)
#pragma unroll
        for (int nt = 0; nt < 8; nt++)
#pragma unroll
            for (int r = 0; r < 4; r++) acc[mt][nt][r] = 0.0f;

    // prologue: stage 0
    {
        float4 a0 = *(const float4*)(Ap + 0);
        float4 a1 = *(const float4*)(Ap + 4);
        float4 b0 = *(const float4*)(Bp + 0);
        float4 b1 = *(const float4*)(Bp + 64);
        uint4 ua0 = {f2tf(a0.x), f2tf(a0.y), f2tf(a0.z), f2tf(a0.w)};
        uint4 ua1 = {f2tf(a1.x), f2tf(a1.y), f2tf(a1.z), f2tf(a1.w)};
        uint4 ub0 = {f2tf(b0.x), f2tf(b0.y), f2tf(b0.z), f2tf(b0.w)};
        uint4 ub1 = {f2tf(b1.x), f2tf(b1.y), f2tf(b1.z), f2tf(b1.w)};
        *(uint4*)&As[0][ar * APITCH + ak] = ua0;
        *(uint4*)&As[0][ar * APITCH + ak + 4] = ua1;
        *(uint4*)&Bs[0][br * BPITCH + bc] = ub0;
        *(uint4*)&Bs[0][br * BPITCH + bc + 64] = ub1;
    }
    __syncthreads();

    for (int k0 = 0; k0 < K; k0 += 16) {
        const int buf = (k0 >> 4) & 1;
        const bool has_next = (k0 + 16) < K;
        float4 ra0, ra1, rb0, rb1;
        if (has_next) {
            ra0 = *(const float4*)(Ap + k0 + 16);
            ra1 = *(const float4*)(Ap + k0 + 20);
            rb0 = *(const float4*)(Bp + (size_t)(k0 + 16) * N);
            rb1 = *(const float4*)(Bp + (size_t)(k0 + 16) * N + 64);
        }

        // compute on current buffer
#pragma unroll
        for (int ks = 0; ks < 16; ks += 8) {
            uint32_t af[2][4];
#pragma unroll
            for (int mt = 0; mt < 2; mt++) {
                const int mrow = wy * 32 + mt * 16 + gid;
                af[mt][0] = As[buf][mrow * APITCH + ks + tig];
                af[mt][1] = As[buf][(mrow + 8) * APITCH + ks + tig];
                af[mt][2] = As[buf][mrow * APITCH + ks + tig + 4];
                af[mt][3] = As[buf][(mrow + 8) * APITCH + ks + tig + 4];
            }
            uint32_t bf[8][2];
#pragma unroll
            for (int nt = 0; nt < 8; nt++) {
                const int nc = wx * 64 + nt * 8 + gid;
                bf[nt][0] = Bs[buf][(ks + tig) * BPITCH + nc];
                bf[nt][1] = Bs[buf][(ks + tig + 4) * BPITCH + nc];
            }
#pragma unroll
            for (int mt = 0; mt < 2; mt++)
#pragma unroll
                for (int nt = 0; nt < 8; nt++)
                    mma_tf32(acc[mt][nt], af[mt], bf[nt]);
        }

        if (has_next) {
            const int nb = buf ^ 1;
            uint4 ua0 = {f2tf(ra0.x), f2tf(ra0.y), f2tf(ra0.z), f2tf(ra0.w)};
            uint4 ua1 = {f2tf(ra1.x), f2tf(ra1.y), f2tf(ra1.z), f2tf(ra1.w)};
            uint4 ub0 = {f2tf(rb0.x), f2tf(rb0.y), f2tf(rb0.z), f2tf(rb0.w)};
            uint4 ub1 = {f2tf(rb1.x), f2tf(rb1.y), f2tf(rb1.z), f2tf(rb1.w)};
            *(uint4*)&As[nb][ar * APITCH + ak] = ua0;
            *(uint4*)&As[nb][ar * APITCH + ak + 4] = ua1;
            *(uint4*)&Bs[nb][br * BPITCH + bc] = ub0;
            *(uint4*)&Bs[nb][br * BPITCH + bc + 64] = ub1;
        }
        __syncthreads();
    }

    // epilogue
#pragma unroll
    for (int mt = 0; mt < 2; mt++) {
#pragma unroll
        for (int nt = 0; nt < 8; nt++) {
            const int col = bn + wx * 64 + nt * 8 + 2 * tig;
            float bv0 = 0.0f, bv1 = 0.0f;
            if (bias) { bv0 = bias[col]; bv1 = bias[col + 1]; }
#pragma unroll
            for (int half = 0; half < 2; half++) {
                const int row = bm + wy * 32 + mt * 16 + gid + half * 8;
                float v0 = acc[mt][nt][half * 2 + 0] + bv0;
                float v1 = acc[mt][nt][half * 2 + 1] + bv1;
                if (mode == EPI_RESID) {
                    v0 += resid[(size_t)row * N + col];
                    v1 += resid[(size_t)row * N + col + 1];
                } else if (mode == EPI_RELU) {
                    v0 = fmaxf(v0, 0.0f);
                    v1 = fmaxf(v1, 0.0f);
                }
                if (mode == EPI_QKV) {
                    const int b = row >> 9, ii = row & 511;
                    const int h = col >> 6, d = col & 63;
                    float2 vv = {v0, v1};
                    *(float2*)&g_q[0] ; // dummy no-op avoided; direct store below
                    *(float2*)(C + (((size_t)(b * CH + h) * CS) + ii) * CD + d) = vv;
                } else {
                    float2 vv = {v0, v1};
                    *(float2*)(C + (size_t)row * N + col) = vv;
                }
            }
        }
    }
}

// ---------------- pad pos_emb into g_pe ---------------------------------------
__global__ void pe_copy_kernel(const float* __restrict__ pe)
{
    int t = blockIdx.x * 256 + threadIdx.x;
    if (t < CNR * CD) g_pe[t] = pe[t];
}

// ---------------- qz table: (BH*S, 129) = Q2d(32768x64) @ pos_emb^T -----------
__global__ __launch_bounds__(256) void qz_kernel(const float* __restrict__ pe)
{
    const int m0 = blockIdx.x << 5;  // 32 q rows
    __shared__ float Qs[32 * 64];
    __shared__ float PEs[CNR * 64];
    const int tid = threadIdx.x;

    const float4* qsrc = (const float4*)(g_q + (size_t)m0 * CD);
    float4* qdst = (float4*)Qs;
    for (int t = tid; t < 32 * 16; t += 256) qdst[t] = qsrc[t];
    const float4* psrc = (const float4*)pe;
    float4* pdst = (float4*)PEs;
    for (int t = tid; t < CNR * 16; t += 256) pdst[t] = psrc[t];
    __syncthreads();

    for (int o = tid; o < 32 * CNR; o += 256) {
        const int i = o / CNR;
        const int r = o - i * CNR;
        const float* qq = Qs + i * 64;
        const float* pp = PEs + r * 64;
        float s = 0.0f;
#pragma unroll
        for (int d = 0; d < 64; d++) s = fmaf(qq[d], pp[d], s);
        g_qz[(size_t)(m0 + i) * CNR + r] = s;
    }
}

// ---------------- scores: w = (q.k + qz[idx])*scale + 0.6*dist, mask ----------
__global__ __launch_bounds__(256) void scores_kernel(
    const float* __restrict__ dist, const int* __restrict__ dt,
    const int* __restrict__ mask)
{
    const int bh = blockIdx.z;
    const int b = bh >> 3;
    const int i0 = blockIdx.y << 6;
    const int j0 = blockIdx.x << 6;

    __shared__ float Qt[64][68];   // [d][i]
    __shared__ float Kt[64][68];   // [d][j]
    __shared__ int dti[64], dtj[64], mj[64];

    const float* qb = g_q + (size_t)bh * CS * CD;
    const float* kb = g_k + (size_t)bh * CS * CD;
    const int tid = threadIdx.x;

#pragma unroll
    for (int l = 0; l < 4; l++) {
        const int idx = tid + (l << 8);
        const int r = idx >> 4;
        const int c = (idx & 15) << 2;
        float4 qv = *(const float4*)(qb + (size_t)(i0 + r) * CD + c);
        float4 kv = *(const float4*)(kb + (size_t)(j0 + r) * CD + c);
        Qt[c + 0][r] = qv.x; Qt[c + 1][r] = qv.y; Qt[c + 2][r] = qv.z; Qt[c + 3][r] = qv.w;
        Kt[c + 0][r] = kv.x; Kt[c + 1][r] = kv.y; Kt[c + 2][r] = kv.z; Kt[c + 3][r] = kv.w;
    }
    if (tid < 64) {
        dti[tid] = dt[b * CS + i0 + tid];
        dtj[tid] = dt[b * CS + j0 + tid];
        mj[tid] = mask[b * CS + j0 + tid];
    }
    __syncthreads();

    const int ty4 = (tid >> 4) << 2;   // i
    const int tx4 = (tid & 15) << 2;   // j
    float acc[4][4];
#pragma unroll
    for (int i = 0; i < 4; i++)
#pragma unroll
        for (int j = 0; j < 4; j++) acc[i][j] = 0.0f;

#pragma unroll
    for (int k = 0; k < 64; k++) {
        float4 a4 = *(const float4*)&Qt[k][ty4];
        float4 b4 = *(const float4*)&Kt[k][tx4];
        float ar[4] = {a4.x, a4.y, a4.z, a4.w};
        float br[4] = {b4.x, b4.y, b4.z, b4.w};
#pragma unroll
        for (int i = 0; i < 4; i++)
#pragma unroll
            for (int j = 0; j < 4; j++)
                acc[i][j] = fmaf(ar[i], br[j], acc[i][j]);
    }

#pragma unroll
    for (int ii = 0; ii < 4; ii++) {
        const int i = i0 + ty4 + ii;
        const int di = dti[ty4 + ii];
#pragma unroll
        for (int jj = 0; jj < 4; jj++) {
            const int j = j0 + tx4 + jj;
            int rel = dtj[tx4 + jj] - di;
            rel = min(max(rel, -CP), CP) + CP;
            const float qzv = g_qz[((size_t)bh * CS + i) * CNR + rel];
            float v = (acc[ii][jj] + qzv) * 0.125f
                    + 0.6f * dist[((size_t)b * CS + i) * CS + j];
            if (mj[tx4 + jj] == 0) v = -1e9f;
            g_w[((size_t)bh * CS + i) * CS + j] = v;
        }
    }
}

// ---------------- softmax + 129-bin histogram ---------------------------------
__global__ __launch_bounds__(256) void softmax_kernel(const int* __restrict__ dt)
{
    const int row = blockIdx.x;           // bh*S + i
    const int bh = row >> 9;
    const int i = row & 511;
    const int b = bh >> 3;
    float* wr = g_w + (size_t)row * CS;
    const int tid = threadIdx.x;

    __shared__ float red[256];
    __shared__ float bins[CNR];

    float v0 = wr[tid], v1 = wr[tid + 256];
    red[tid] = fmaxf(v0, v1);
    __syncthreads();
    for (int s = 128; s > 0; s >>= 1) {
        if (tid < s) red[tid] = fmaxf(red[tid], red[tid + s]);
        __syncthreads();
    }
    const float mx = red[0];
    __syncthreads();

    const float e0 = __expf(v0 - mx);
    const float e1 = __expf(v1 - mx);
    red[tid] = e0 + e1;
    __syncthreads();
    for (int s = 128; s > 0; s >>= 1) {
        if (tid < s) red[tid] += red[tid + s];
        __syncthreads();
    }
    const float inv = 1.0f / red[0];
    if (tid < CNR) bins[tid] = 0.0f;
    __syncthreads();

    const float a0 = e0 * inv, a1 = e1 * inv;
    wr[tid] = a0;
    wr[tid + 256] = a1;

    const int di = dt[b * CS + i];
    int r0 = min(max(dt[b * CS + tid] - di, -CP), CP) + CP;
    int r1 = min(max(dt[b * CS + tid + 256] - di, -CP), CP) + CP;
    atomicAdd(&bins[r0], a0);
    atomicAdd(&bins[r1], a1);
    __syncthreads();
    if (tid < CNR) g_s[(size_t)row * CSR + tid] = bins[tid];
}

// ---------------- attn = aw@v + bins@pos_emb -> concat layout -----------------
__global__ __launch_bounds__(256) void attn_kernel()
{
    const int bh = blockIdx.y;
    const int b = bh >> 3, h = bh & 7;
    const int i0 = blockIdx.x << 6;
    const int tid = threadIdx.x;

    __shared__ float At[64][68];   // [k][i]
    __shared__ float Vs[64][64];   // [k][d]

    const float* awb = g_w + (size_t)bh * CS * CS;
    const float* sb = g_s + (size_t)bh * CS * CSR;
    const float* vb = g_v + (size_t)bh * CS * CD;

    const int ty4 = (tid >> 4) << 2;   // i
    const int tx4 = (tid & 15) << 2;   // d
    float acc[4][4];
#pragma unroll
    for (int i = 0; i < 4; i++)
#pragma unroll
        for (int j = 0; j < 4; j++) acc[i][j] = 0.0f;

    for (int c = 0; c < 11; c++) {
#pragma unroll
        for (int l = 0; l < 4; l++) {
            const int idx = tid + (l << 8);
            const int r = idx >> 4;
            const int cc = (idx & 15) << 2;
            float4 av, vv;
            if (c < 8) {
                av = *(const float4*)(awb + (size_t)(i0 + r) * CS + (c << 6) + cc);
                vv = *(const float4*)(vb + (size_t)((c << 6) + r) * CD + cc);
            } else {
                av = *(const float4*)(sb + (size_t)(i0 + r) * CSR + ((c - 8) << 6) + cc);
                vv = *(const float4*)(g_pe + (size_t)(((c - 8) << 6) + r) * CD + cc);
            }
            At[cc + 0][r] = av.x; At[cc + 1][r] = av.y; At[cc + 2][r] = av.z; At[cc + 3][r] = av.w;
            *(float4*)&Vs[r][cc] = vv;
        }
        __syncthreads();
#pragma unroll
        for (int k = 0; k < 64; k++) {
            float4 a4 = *(const float4*)&At[k][ty4];
            float4 v4 = *(const float4*)&Vs[k][tx4];
            float ar[4] = {a4.x, a4.y, a4.z, a4.w};
            float vr[4] = {v4.x, v4.y, v4.z, v4.w};
#pragma unroll
            for (int i = 0; i < 4; i++)
#pragma unroll
                for (int j = 0; j < 4; j++)
                    acc[i][j] = fmaf(ar[i], vr[j], acc[i][j]);
        }
        __syncthreads();
    }

#pragma unroll
    for (int ii = 0; ii < 4; ii++)
#pragma unroll
        for (int jj = 0; jj < 4; jj++)
            g_concat[(size_t)(b * CS + i0 + ty4 + ii) * CE + h * CD + tx4 + jj] = acc[ii][jj];
}

// ---------------- layernorm (row = 512) ---------------------------------------
__global__ __launch_bounds__(256) void ln_kernel(
    const float* __restrict__ in, float* __restrict__ out,
    const float* __restrict__ gg, const float* __restrict__ bb)
{
    const int row = blockIdx.x;
    const float* xr = in + (size_t)row * CE;
    const int tid = threadIdx.x;
    __shared__ float red[256];

    float v0 = xr[tid], v1 = xr[tid + 256];
    red[tid] = v0 + v1;
    __syncthreads();
    for (int s = 128; s > 0; s >>= 1) {
        if (tid < s) red[tid] += red[tid + s];
        __syncthreads();
    }
    const float mu = red[0] * (1.0f / CE);
    __syncthreads();
    const float d0 = v0 - mu, d1 = v1 - mu;
    red[tid] = d0 * d0 + d1 * d1;
    __syncthreads();
    for (int s = 128; s > 0; s >>= 1) {
        if (tid < s) red[tid] += red[tid + s];
        __syncthreads();
    }
    const float rstd = rsqrtf(red[0] * (1.0f / CE) + 1e-5f);
    out[(size_t)row * CE + tid] = d0 * rstd * gg[tid] + bb[tid];
    out[(size_t)row * CE + tid + 256] = d1 * rstd * gg[tid + 256] + bb[tid + 256];
}

// ---------------- launch -------------------------------------------------------
extern "C" void kernel_launch(void* const* d_in, const int* in_sizes, int n_in,
                              void* d_out, int out_size)
{
    const float* x    = (const float*)d_in[0];
    const float* dist = (const float*)d_in[1];
    const int*   dt   = (const int*)d_in[2];
    const int*   mask = (const int*)d_in[3];
    const float* wq_w = (const float*)d_in[4];
    const float* wq_b = (const float*)d_in[5];
    const float* wk_w = (const float*)d_in[6];
    const float* wk_b = (const float*)d_in[7];
    const float* wv_w = (const float*)d_in[8];
    const float* wv_b = (const float*)d_in[9];
    const float* wo_w = (const float*)d_in[10];
    const float* wo_b = (const float*)d_in[11];
    const float* pe   = (const float*)d_in[12];
    const float* w1   = (const float*)d_in[13];
    const float* b1   = (const float*)d_in[14];
    const float* w2   = (const float*)d_in[15];
    const float* b2   = (const float*)d_in[16];
    const float* ln1g = (const float*)d_in[17];
    const float* ln1b = (const float*)d_in[18];
    const float* ln2g = (const float*)d_in[19];
    const float* ln2b = (const float*)d_in[20];
    float* out = (float*)d_out;

    void *pq, *pk, *pv, *pcc, *pt1, *pao, *phid, *pt2;
    cudaGetSymbolAddress(&pq, g_q);
    cudaGetSymbolAddress(&pk, g_k);
    cudaGetSymbolAddress(&pv, g_v);
    cudaGetSymbolAddress(&pcc, g_concat);
    cudaGetSymbolAddress(&pt1, g_t1);
    cudaGetSymbolAddress(&pao, g_attnout);
    cudaGetSymbolAddress(&phid, g_hidden);
    cudaGetSymbolAddress(&pt2, g_t2);

    pe_copy_kernel<<<(CNR * CD + 255) / 256, 256>>>(pe);

    dim3 gqkv(CE / 128, CM / 128);
    mma_gemm_kernel<<<gqkv, 256>>>(x, wq_w, (float*)pq, CM, CE, CE, wq_b, nullptr, EPI_QKV);
    mma_gemm_kernel<<<gqkv, 256>>>(x, wk_w, (float*)pk, CM, CE, CE, wk_b, nullptr, EPI_QKV);
    mma_gemm_kernel<<<gqkv, 256>>>(x, wv_w, (float*)pv, CM, CE, CE, wv_b, nullptr, EPI_QKV);

    qz_kernel<<<(CBH * CS) / 32, 256>>>(pe);

    dim3 gsc(CS / 64, CS / 64, CBH);
    scores_kernel<<<gsc, 256>>>(dist, dt, mask);

    softmax_kernel<<<CBH * CS, 256>>>(dt);

    dim3 gat(CS / 64, CBH);
    attn_kernel<<<gat, 256>>>();

    mma_gemm_kernel<<<gqkv, 256>>>((const float*)pcc, wo_w, (float*)pt1, CM, CE, CE, wo_b, x, EPI_RESID);
    ln_kernel<<<CM, 256>>>((const float*)pt1, (float*)pao, ln1g, ln1b);

    dim3 gf1(CF / 128, CM / 128);
    mma_gemm_kernel<<<gf1, 256>>>((const float*)pao, w1, (float*)phid, CM, CF, CE, b1, nullptr, EPI_RELU);
    mma_gemm_kernel<<<gqkv, 256>>>((const float*)phid, w2, (float*)pt2, CM, CE, CF, b2, (const float*)pao, EPI_RESID);
    ln_kernel<<<CM, 256>>>((const float*)pt2, out, ln2g, ln2b);
}